// round 7
// baseline (speedup 1.0000x reference)
#include <cuda_runtime.h>

#define N_NODES 50000
#define E_EDGES 800000
#define FEAT    512
#define HID     256
#define CLS     40
#define EPSV    1e-5f

// ---------------- scratch (device globals: no runtime allocation) ----------------
__device__ int   g_degi[N_NODES];
__device__ float g_inv[N_NODES];
__device__ int   g_src[E_EDGES];
__device__ int   g_dst[E_EDGES];
__device__ int   g_rowptr[N_NODES + 1];
__device__ int   g_fill[N_NODES];
__device__ int   g_csrc[E_EDGES + N_NODES];
__device__ float g_cw[E_EDGES + N_NODES];
__device__ int   g_is64;
__device__ float g_bufA[(size_t)N_NODES * HID];   // 51.2 MB
__device__ float g_bufB[(size_t)N_NODES * HID];   // 51.2 MB
__device__ float g_bufC[(size_t)N_NODES * CLS];   // 8 MB

// ---------------- prep kernels ----------------

// Detect whether edge_index buffer is int64 or int32.
// If int32 data is misread as int64, values combine two indices -> >= 2^32
// (or generally out of [0,N)) with overwhelming probability across 64 samples.
__global__ void k_detect(const void* eiraw) {
    const long long* e64 = (const long long*)eiraw;
    int t = threadIdx.x;
    long long v = e64[t];
    int ok = (v >= 0 && v < N_NODES) ? 1 : 0;
    unsigned m = __ballot_sync(0xffffffffu, ok);
    if (t == 0) g_is64 = (m == 0xffffffffu) ? 1 : 0;
}

__global__ void k_init() {
    int i = blockIdx.x * blockDim.x + threadIdx.x;
    if (i < N_NODES) g_degi[i] = 1;   // self loop
}

__device__ __forceinline__ int clampN(int v) {
    v = v < 0 ? 0 : v;
    return v >= N_NODES ? N_NODES - 1 : v;
}

__global__ void k_edges(const void* eiraw) {
    int e = blockIdx.x * blockDim.x + threadIdx.x;
    if (e >= E_EDGES) return;
    int s, d;
    if (g_is64) {
        const long long* p = (const long long*)eiraw;
        s = (int)p[e];
        d = (int)p[E_EDGES + e];
    } else {
        const int* p = (const int*)eiraw;
        s = p[e];
        d = p[E_EDGES + e];
    }
    s = clampN(s);
    d = clampN(d);
    g_src[e] = s;
    g_dst[e] = d;
    atomicAdd(&g_degi[d], 1);
}

__global__ void k_inv() {
    int i = blockIdx.x * blockDim.x + threadIdx.x;
    if (i < N_NODES) g_inv[i] = rsqrtf((float)g_degi[i]);
}

// single-block exclusive scan of g_degi -> g_rowptr / g_fill
__global__ void k_scan() {
    __shared__ int wsum[32];
    __shared__ int carry_s;
    int tid = threadIdx.x, lane = tid & 31, wid = tid >> 5;
    if (tid == 0) carry_s = 0;
    __syncthreads();
    for (int start = 0; start < N_NODES; start += 1024) {
        int i = start + tid;
        int v = (i < N_NODES) ? g_degi[i] : 0;
        int x = v;
        #pragma unroll
        for (int o = 1; o < 32; o <<= 1) {
            int t = __shfl_up_sync(0xffffffffu, x, o);
            if (lane >= o) x += t;
        }
        if (lane == 31) wsum[wid] = x;
        __syncthreads();
        if (wid == 0) {
            int s = wsum[lane];
            #pragma unroll
            for (int o = 1; o < 32; o <<= 1) {
                int t = __shfl_up_sync(0xffffffffu, s, o);
                if (lane >= o) s += t;
            }
            wsum[lane] = s;
        }
        __syncthreads();
        int excl = x - v + (wid ? wsum[wid - 1] : 0) + carry_s;
        if (i < N_NODES) { g_rowptr[i] = excl; g_fill[i] = excl; }
        int total = wsum[31];
        __syncthreads();
        if (tid == 0) carry_s += total;
        __syncthreads();
    }
    if (threadIdx.x == 0) g_rowptr[N_NODES] = carry_s;
}

__global__ void k_fill() {
    int idx = blockIdx.x * blockDim.x + threadIdx.x;
    if (idx >= E_EDGES + N_NODES) return;
    if (idx < E_EDGES) {
        int s = g_src[idx], d = g_dst[idx];
        int slot = atomicAdd(&g_fill[d], 1);
        g_csrc[slot] = s;
        g_cw[slot] = g_inv[s] * g_inv[d];
    } else {
        int i = idx - E_EDGES;
        int slot = atomicAdd(&g_fill[i], 1);
        g_csrc[slot] = i;
        float iv = g_inv[i];
        g_cw[slot] = iv * iv;
    }
}

// ---------------- SGEMM (fp32, register-tiled) ----------------
template<int BM, int BN, int BK, int TM, int TN>
__global__ void sgemm(const float* __restrict__ A, const float* __restrict__ B,
                      float* __restrict__ C, int M, int K, int Nn) {
    constexpr int NT = (BM / TM) * (BN / TN);
    __shared__ float As[BK][BM + 4];
    __shared__ float Bs[BK][BN + 4];
    const int tid = threadIdx.x;
    const int tx = tid % (BN / TN);
    const int ty = tid / (BN / TN);
    const int rowBase = blockIdx.y * BM;
    const int colBase = blockIdx.x * BN;

    float acc[TM][TN];
    #pragma unroll
    for (int i = 0; i < TM; i++)
        #pragma unroll
        for (int j = 0; j < TN; j++) acc[i][j] = 0.f;

    for (int k0 = 0; k0 < K; k0 += BK) {
        for (int i = tid; i < BM * BK / 4; i += NT) {
            int r = i / (BK / 4), kq = i % (BK / 4);
            int gr = rowBase + r;
            float4 v = make_float4(0.f, 0.f, 0.f, 0.f);
            if (gr < M)
                v = *reinterpret_cast<const float4*>(A + (size_t)gr * K + k0 + kq * 4);
            As[kq * 4 + 0][r] = v.x;
            As[kq * 4 + 1][r] = v.y;
            As[kq * 4 + 2][r] = v.z;
            As[kq * 4 + 3][r] = v.w;
        }
        for (int i = tid; i < BK * BN / 4; i += NT) {
            int kk = i / (BN / 4), cq = i % (BN / 4);
            *reinterpret_cast<float4*>(&Bs[kk][cq * 4]) =
                *reinterpret_cast<const float4*>(B + (size_t)(k0 + kk) * Nn + colBase + cq * 4);
        }
        __syncthreads();
        #pragma unroll
        for (int kk = 0; kk < BK; kk++) {
            float a[TM], b[TN];
            #pragma unroll
            for (int i = 0; i < TM; i += 4) {
                float4 v = *reinterpret_cast<const float4*>(&As[kk][ty * TM + i]);
                a[i] = v.x; a[i + 1] = v.y; a[i + 2] = v.z; a[i + 3] = v.w;
            }
            #pragma unroll
            for (int j = 0; j < TN; j += 4) {
                float4 v = *reinterpret_cast<const float4*>(&Bs[kk][tx * TN + j]);
                b[j] = v.x; b[j + 1] = v.y; b[j + 2] = v.z; b[j + 3] = v.w;
            }
            #pragma unroll
            for (int i = 0; i < TM; i++)
                #pragma unroll
                for (int j = 0; j < TN; j++)
                    acc[i][j] = fmaf(a[i], b[j], acc[i][j]);
        }
        __syncthreads();
    }
    #pragma unroll
    for (int i = 0; i < TM; i++) {
        int gr = rowBase + ty * TM + i;
        if (gr < M) {
            #pragma unroll
            for (int j = 0; j < TN; j += 4) {
                float4 v = make_float4(acc[i][j], acc[i][j + 1], acc[i][j + 2], acc[i][j + 3]);
                *reinterpret_cast<float4*>(C + (size_t)gr * Nn + colBase + tx * TN + j) = v;
            }
        }
    }
}

// ---------------- aggregation (CSR gather, warp per destination row) ----------------
__device__ __forceinline__ void fma4(float4& a, const float4& v, float w) {
    a.x = fmaf(v.x, w, a.x);
    a.y = fmaf(v.y, w, a.y);
    a.z = fmaf(v.z, w, a.z);
    a.w = fmaf(v.w, w, a.w);
}

// 256-wide aggregation + bias + BN(inference) + ReLU, fused epilogue
__global__ void agg_hid(const float* __restrict__ hin, float* __restrict__ hout,
                        const float* __restrict__ bias, const float* __restrict__ gamma,
                        const float* __restrict__ beta, const float* __restrict__ mean,
                        const float* __restrict__ var) {
    int row = blockIdx.x * (blockDim.x >> 5) + (threadIdx.x >> 5);
    if (row >= N_NODES) return;
    int lane = threadIdx.x & 31;
    int beg = g_rowptr[row], end = g_rowptr[row + 1];
    float4 a0 = make_float4(0.f, 0.f, 0.f, 0.f), a1 = a0;
    for (int p = beg; p < end; p++) {
        int s = g_csrc[p];
        float w = g_cw[p];
        const float4* r = reinterpret_cast<const float4*>(hin + (size_t)s * HID);
        float4 v0 = r[lane];
        float4 v1 = r[lane + 32];
        fma4(a0, v0, w);
        fma4(a1, v1, w);
    }
    const float4* b4 = reinterpret_cast<const float4*>(bias);
    const float4* g4 = reinterpret_cast<const float4*>(gamma);
    const float4* be4 = reinterpret_cast<const float4*>(beta);
    const float4* m4 = reinterpret_cast<const float4*>(mean);
    const float4* v4 = reinterpret_cast<const float4*>(var);
    float4* outr = reinterpret_cast<float4*>(hout + (size_t)row * HID);
    #pragma unroll
    for (int h = 0; h < 2; h++) {
        int f = lane + 32 * h;
        float4 acc = h ? a1 : a0;
        float4 bb = b4[f], gg = g4[f], ee = be4[f], mm = m4[f], vv = v4[f];
        float4 o;
        o.x = fmaxf(0.f, (acc.x + bb.x - mm.x) * rsqrtf(vv.x + EPSV) * gg.x + ee.x);
        o.y = fmaxf(0.f, (acc.y + bb.y - mm.y) * rsqrtf(vv.y + EPSV) * gg.y + ee.y);
        o.z = fmaxf(0.f, (acc.z + bb.z - mm.z) * rsqrtf(vv.z + EPSV) * gg.z + ee.z);
        o.w = fmaxf(0.f, (acc.w + bb.w - mm.w) * rsqrtf(vv.w + EPSV) * gg.w + ee.w);
        outr[f] = o;
    }
}

// 40-wide aggregation + bias (final layer, writes every element of d_out)
__global__ void agg_out(const float* __restrict__ hin, float* __restrict__ hout,
                        const float* __restrict__ bias) {
    int row = blockIdx.x * (blockDim.x >> 5) + (threadIdx.x >> 5);
    if (row >= N_NODES) return;
    int lane = threadIdx.x & 31;
    int beg = g_rowptr[row], end = g_rowptr[row + 1];
    bool act = lane < (CLS / 4);
    float4 a = make_float4(0.f, 0.f, 0.f, 0.f);
    for (int p = beg; p < end; p++) {
        int s = g_csrc[p];
        float w = g_cw[p];
        if (act) {
            float4 v = reinterpret_cast<const float4*>(hin + (size_t)s * CLS)[lane];
            fma4(a, v, w);
        }
    }
    if (act) {
        float4 b = reinterpret_cast<const float4*>(bias)[lane];
        a.x += b.x; a.y += b.y; a.z += b.z; a.w += b.w;
        reinterpret_cast<float4*>(hout + (size_t)row * CLS)[lane] = a;
    }
}

// ---------------- launch ----------------
extern "C" void kernel_launch(void* const* d_in, const int* in_sizes, int n_in,
                              void* d_out, int out_size) {
    const float*     x     = (const float*)d_in[0];
    const void*      ei    = (const void*)d_in[1];
    const float*     W1    = (const float*)d_in[2];
    const float*     b1    = (const float*)d_in[3];
    const float*     W2    = (const float*)d_in[4];
    const float*     b2    = (const float*)d_in[5];
    const float*     W3    = (const float*)d_in[6];
    const float*     b3    = (const float*)d_in[7];
    const float*     gamma = (const float*)d_in[8];
    const float*     beta  = (const float*)d_in[9];
    const float*     mean  = (const float*)d_in[10];
    const float*     var   = (const float*)d_in[11];
    float* out = (float*)d_out;

    float *pA, *pB, *pC;
    cudaGetSymbolAddress((void**)&pA, g_bufA);
    cudaGetSymbolAddress((void**)&pB, g_bufB);
    cudaGetSymbolAddress((void**)&pC, g_bufC);

    // graph prep
    k_detect<<<1, 64>>>(ei);
    k_init<<<(N_NODES + 255) / 256, 256>>>();
    k_edges<<<(E_EDGES + 255) / 256, 256>>>(ei);
    k_inv<<<(N_NODES + 255) / 256, 256>>>();
    k_scan<<<1, 1024>>>();
    k_fill<<<(E_EDGES + N_NODES + 255) / 256, 256>>>();

    // layer 1: X @ W1 -> bufA ; aggregate+BN+ReLU -> bufB
    {
        dim3 g(HID / 64, (N_NODES + 127) / 128);
        sgemm<128, 64, 16, 8, 4><<<g, 256>>>(x, W1, pA, N_NODES, FEAT, HID);
    }
    agg_hid<<<(N_NODES + 7) / 8, 256>>>(pA, pB, b1, gamma, beta, mean, var);

    // layer 2
    {
        dim3 g(HID / 64, (N_NODES + 127) / 128);
        sgemm<128, 64, 16, 8, 4><<<g, 256>>>(pB, W2, pA, N_NODES, HID, HID);
    }
    agg_hid<<<(N_NODES + 7) / 8, 256>>>(pA, pB, b2, gamma, beta, mean, var);

    // layer 3: bufB @ W3 -> bufC ; aggregate + b3 -> out
    {
        dim3 g(1, (N_NODES + 127) / 128);
        sgemm<128, 40, 16, 8, 4><<<g, 160>>>(pB, W3, pC, N_NODES, HID, CLS);
    }
    agg_out<<<(N_NODES + 7) / 8, 256>>>(pC, out, b3);
}

// round 9
// speedup vs baseline: 1.5351x; 1.5351x over previous
#include <cuda_runtime.h>
#include <cuda_bf16.h>
#include <cstdint>

#define N_NODES 50000
#define E_EDGES 800000
#define FEAT    512
#define HID     256
#define CLS     40
#define EPSV    1e-5f

#define SWZ128(o) ((o) ^ (((o) >> 3) & 0x70))

// ==================== baseline PTX helpers (compute_103-safe) ====================
__device__ __forceinline__ uint32_t smem_u32(const void* p) {
    uint32_t a;
    asm("{ .reg .u64 t; cvta.to.shared.u64 t, %1; cvt.u32.u64 %0, t; }" : "=r"(a) : "l"(p));
    return a;
}
__device__ __forceinline__ void ldsm_x4(uint32_t& r0, uint32_t& r1, uint32_t& r2, uint32_t& r3,
                                        uint32_t addr) {
    asm volatile("ldmatrix.sync.aligned.m8n8.x4.shared.b16 {%0,%1,%2,%3}, [%4];"
                 : "=r"(r0), "=r"(r1), "=r"(r2), "=r"(r3) : "r"(addr));
}
__device__ __forceinline__ void mma_bf16(float* c, const uint32_t* a, const uint32_t* b) {
    asm volatile(
        "mma.sync.aligned.m16n8k16.row.col.f32.bf16.bf16.f32 "
        "{%0,%1,%2,%3}, {%4,%5,%6,%7}, {%8,%9}, {%0,%1,%2,%3};"
        : "+f"(c[0]), "+f"(c[1]), "+f"(c[2]), "+f"(c[3])
        : "r"(a[0]), "r"(a[1]), "r"(a[2]), "r"(a[3]), "r"(b[0]), "r"(b[1]));
}
__device__ __forceinline__ void cp_async16(uint32_t dst, const void* src) {
    asm volatile("cp.async.cg.shared.global [%0], [%1], 16;" :: "r"(dst), "l"(src) : "memory");
}
#define CP_COMMIT() asm volatile("cp.async.commit_group;" ::: "memory")
#define CP_WAIT1()  asm volatile("cp.async.wait_group 1;" ::: "memory")
#define CP_WAIT0()  asm volatile("cp.async.wait_group 0;" ::: "memory")

// ==================== scratch (device globals) ====================
__device__ int   g_degi[N_NODES];
__device__ float g_inv[N_NODES];
__device__ int   g_src[E_EDGES];
__device__ int   g_dst[E_EDGES];
__device__ int   g_rowptr[N_NODES + 1];
__device__ int   g_fill[N_NODES];
__device__ int   g_csrc[E_EDGES + N_NODES];
__device__ float g_cw[E_EDGES + N_NODES];
__device__ int   g_is64;
__device__ float g_bufA[(size_t)N_NODES * HID];
__device__ float g_bufB[(size_t)N_NODES * HID];
__device__ float g_bufC[(size_t)N_NODES * CLS];
__device__ __nv_bfloat16 g_Xhi[(size_t)N_NODES * FEAT];
__device__ __nv_bfloat16 g_Xlo[(size_t)N_NODES * FEAT];
__device__ __nv_bfloat16 g_W1hi[HID * FEAT];
__device__ __nv_bfloat16 g_W1lo[HID * FEAT];
__device__ __nv_bfloat16 g_W2hi[HID * HID];
__device__ __nv_bfloat16 g_W2lo[HID * HID];

// ==================== prep kernels ====================
__global__ void k_detect(const void* eiraw) {
    const long long* e64 = (const long long*)eiraw;
    int t = threadIdx.x;
    long long v = e64[t];
    int ok = (v >= 0 && v < N_NODES) ? 1 : 0;
    unsigned m = __ballot_sync(0xffffffffu, ok);
    if (t == 0) g_is64 = (m == 0xffffffffu) ? 1 : 0;
}
__global__ void k_init() {
    int i = blockIdx.x * blockDim.x + threadIdx.x;
    if (i < N_NODES) g_degi[i] = 1;
}
__device__ __forceinline__ int clampN(int v) {
    v = v < 0 ? 0 : v;
    return v >= N_NODES ? N_NODES - 1 : v;
}
__global__ void k_edges(const void* eiraw) {
    int e = blockIdx.x * blockDim.x + threadIdx.x;
    if (e >= E_EDGES) return;
    int s, d;
    if (g_is64) {
        const long long* p = (const long long*)eiraw;
        s = (int)p[e]; d = (int)p[E_EDGES + e];
    } else {
        const int* p = (const int*)eiraw;
        s = p[e]; d = p[E_EDGES + e];
    }
    s = clampN(s); d = clampN(d);
    g_src[e] = s; g_dst[e] = d;
    atomicAdd(&g_degi[d], 1);
}
__global__ void k_inv() {
    int i = blockIdx.x * blockDim.x + threadIdx.x;
    if (i < N_NODES) g_inv[i] = rsqrtf((float)g_degi[i]);
}
__global__ void k_scan() {
    __shared__ int wsum[32];
    __shared__ int carry_s;
    int tid = threadIdx.x, lane = tid & 31, wid = tid >> 5;
    if (tid == 0) carry_s = 0;
    __syncthreads();
    for (int start = 0; start < N_NODES; start += 1024) {
        int i = start + tid;
        int v = (i < N_NODES) ? g_degi[i] : 0;
        int x = v;
        #pragma unroll
        for (int o = 1; o < 32; o <<= 1) {
            int t = __shfl_up_sync(0xffffffffu, x, o);
            if (lane >= o) x += t;
        }
        if (lane == 31) wsum[wid] = x;
        __syncthreads();
        if (wid == 0) {
            int s = wsum[lane];
            #pragma unroll
            for (int o = 1; o < 32; o <<= 1) {
                int t = __shfl_up_sync(0xffffffffu, s, o);
                if (lane >= o) s += t;
            }
            wsum[lane] = s;
        }
        __syncthreads();
        int excl = x - v + (wid ? wsum[wid - 1] : 0) + carry_s;
        if (i < N_NODES) { g_rowptr[i] = excl; g_fill[i] = excl; }
        int total = wsum[31];
        __syncthreads();
        if (tid == 0) carry_s += total;
        __syncthreads();
    }
    if (threadIdx.x == 0) g_rowptr[N_NODES] = carry_s;
}
__global__ void k_fill() {
    int idx = blockIdx.x * blockDim.x + threadIdx.x;
    if (idx >= E_EDGES + N_NODES) return;
    if (idx < E_EDGES) {
        int s = g_src[idx], d = g_dst[idx];
        int slot = atomicAdd(&g_fill[d], 1);
        g_csrc[slot] = s;
        g_cw[slot] = g_inv[s] * g_inv[d];
    } else {
        int i = idx - E_EDGES;
        int slot = atomicAdd(&g_fill[i], 1);
        g_csrc[slot] = i;
        float iv = g_inv[i];
        g_cw[slot] = iv * iv;
    }
}

// ==================== fp32 -> bf16 hi/lo split ====================
__device__ __forceinline__ uint32_t pack_bf2(float a, float b) {
    return (uint32_t)__bfloat16_as_ushort(__float2bfloat16_rn(a)) |
           ((uint32_t)__bfloat16_as_ushort(__float2bfloat16_rn(b)) << 16);
}
__device__ __forceinline__ void split1(float x, float& hi, float& lo) {
    __nv_bfloat16 h = __float2bfloat16_rn(x);
    hi = __bfloat162float(h);
    lo = x - hi;
}

__global__ void k_cvtX(const float* __restrict__ x,
                       __nv_bfloat16* __restrict__ ohi, __nv_bfloat16* __restrict__ olo) {
    size_t i = (size_t)blockIdx.x * blockDim.x + threadIdx.x;
    size_t total = (size_t)N_NODES * FEAT / 4;
    if (i >= total) return;
    float4 v = reinterpret_cast<const float4*>(x)[i];
    float h0, l0, h1, l1, h2, l2, h3, l3;
    split1(v.x, h0, l0); split1(v.y, h1, l1); split1(v.z, h2, l2); split1(v.w, h3, l3);
    uint2 hh, ll;
    hh.x = pack_bf2(h0, h1); hh.y = pack_bf2(h2, h3);
    ll.x = pack_bf2(l0, l1); ll.y = pack_bf2(l2, l3);
    reinterpret_cast<uint2*>(ohi)[i] = hh;
    reinterpret_cast<uint2*>(olo)[i] = ll;
}

// W [K, Nn] fp32 -> W^T hi/lo bf16 [Nn, K]
__global__ void k_cvtW(const float* __restrict__ W, __nv_bfloat16* __restrict__ ohi,
                       __nv_bfloat16* __restrict__ olo, int K, int Nn) {
    int i = blockIdx.x * blockDim.x + threadIdx.x;
    if (i >= K * Nn) return;
    int k = i / Nn, n = i % Nn;
    float h, l;
    split1(W[i], h, l);
    ohi[(size_t)n * K + k] = __float2bfloat16_rn(h);
    olo[(size_t)n * K + k] = __float2bfloat16_rn(l);
}

// ==================== mma.sync split-bf16 GEMM ====================
// C[M x 256] = A[M x KTOT] * B^T, B stored [256 x KTOT] (n-major).
// CTA tile 128x128, 8 warps (warp tile 32x64), K-chunk 64, 2-stage cp.async.
#define KC        64
#define TILE_B    16384                 // one 128x64 bf16 tile, swizzled
#define STG_BYTES (4 * TILE_B)          // Ahi, Alo, Bhi, Blo
#define G_SMEM    (2 * STG_BYTES)       // 131072

__global__ void __launch_bounds__(256, 1)
gemm_mma(const __nv_bfloat16* __restrict__ Ahi, const __nv_bfloat16* __restrict__ Alo,
         const __nv_bfloat16* __restrict__ Bhi, const __nv_bfloat16* __restrict__ Blo,
         float* __restrict__ C, int M, int KTOT) {
    extern __shared__ char sm[];
    const int tid = threadIdx.x, lane = tid & 31, wid = tid >> 5;
    const int rowBase = blockIdx.x * 128, colBase = blockIdx.y * 128;
    const int wm = wid >> 1, wn = wid & 1;
    const int nch = KTOT / KC;

    auto issue = [&](int c) {
        int k0 = c * KC;
        char* base = sm + (c & 1) * STG_BYTES;
        #pragma unroll
        for (int u = tid; u < 1024; u += 256) {
            int r = u >> 3, q = u & 7;
            int gr = rowBase + r;
            if (gr >= M) gr = M - 1;
            size_t ga = (size_t)gr * KTOT + k0 + q * 8;
            size_t gb = (size_t)(colBase + r) * KTOT + k0 + q * 8;
            uint32_t off = SWZ128((r << 7) + (q << 4));
            cp_async16(smem_u32(base + off), Ahi + ga);
            cp_async16(smem_u32(base + TILE_B + off), Alo + ga);
            cp_async16(smem_u32(base + 2 * TILE_B + off), Bhi + gb);
            cp_async16(smem_u32(base + 3 * TILE_B + off), Blo + gb);
        }
        CP_COMMIT();
    };

    float acc[2][8][4];
    #pragma unroll
    for (int i = 0; i < 2; i++)
        #pragma unroll
        for (int j = 0; j < 8; j++)
            #pragma unroll
            for (int k = 0; k < 4; k++) acc[i][j][k] = 0.f;

    issue(0);
    issue(1);

    for (int c = 0; c < nch; c++) {
        if (c <= nch - 2) { CP_WAIT1(); } else { CP_WAIT0(); }
        __syncthreads();
        char* base = sm + (c & 1) * STG_BYTES;
        uint32_t sA_hi = smem_u32(base);
        uint32_t sA_lo = sA_hi + TILE_B;
        uint32_t sB_hi = sA_hi + 2 * TILE_B;
        uint32_t sB_lo = sA_hi + 3 * TILE_B;
        #pragma unroll
        for (int kk = 0; kk < 4; kk++) {
            uint32_t ah[2][4], al[2][4], bh[8][2], bl[8][2];
            #pragma unroll
            for (int mt = 0; mt < 2; mt++) {
                int row = wm * 32 + mt * 16 + (lane & 15);
                int q = kk * 2 + (lane >> 4);
                uint32_t off = SWZ128((row << 7) + (q << 4));
                ldsm_x4(ah[mt][0], ah[mt][1], ah[mt][2], ah[mt][3], sA_hi + off);
                ldsm_x4(al[mt][0], al[mt][1], al[mt][2], al[mt][3], sA_lo + off);
            }
            #pragma unroll
            for (int ng = 0; ng < 4; ng++) {
                int nr = wn * 64 + ng * 16 + ((lane >> 4) << 3) + (lane & 7);
                int q = kk * 2 + ((lane >> 3) & 1);
                uint32_t off = SWZ128((nr << 7) + (q << 4));
                uint32_t r0, r1, r2, r3;
                ldsm_x4(r0, r1, r2, r3, sB_hi + off);
                bh[ng * 2][0] = r0; bh[ng * 2][1] = r1;
                bh[ng * 2 + 1][0] = r2; bh[ng * 2 + 1][1] = r3;
                ldsm_x4(r0, r1, r2, r3, sB_lo + off);
                bl[ng * 2][0] = r0; bl[ng * 2][1] = r1;
                bl[ng * 2 + 1][0] = r2; bl[ng * 2 + 1][1] = r3;
            }
            #pragma unroll
            for (int mt = 0; mt < 2; mt++)
                #pragma unroll
                for (int nt = 0; nt < 8; nt++) {
                    mma_bf16(acc[mt][nt], ah[mt], bh[nt]);
                    mma_bf16(acc[mt][nt], ah[mt], bl[nt]);
                    mma_bf16(acc[mt][nt], al[mt], bh[nt]);
                }
        }
        __syncthreads();
        if (c + 2 < nch) issue(c + 2);
    }

    // epilogue
    #pragma unroll
    for (int mt = 0; mt < 2; mt++) {
        int row0 = rowBase + wm * 32 + mt * 16 + (lane >> 2);
        #pragma unroll
        for (int nt = 0; nt < 8; nt++) {
            int cc = colBase + wn * 64 + nt * 8 + 2 * (lane & 3);
            if (row0 < M)
                *reinterpret_cast<float2*>(C + (size_t)row0 * 256 + cc) =
                    make_float2(acc[mt][nt][0], acc[mt][nt][1]);
            if (row0 + 8 < M)
                *reinterpret_cast<float2*>(C + (size_t)(row0 + 8) * 256 + cc) =
                    make_float2(acc[mt][nt][2], acc[mt][nt][3]);
        }
    }
}

// ==================== fp32 SGEMM (layer 3 only) ====================
template<int BM, int BN, int BK, int TM, int TN>
__global__ void sgemm(const float* __restrict__ A, const float* __restrict__ B,
                      float* __restrict__ C, int M, int K, int Nn) {
    constexpr int NT = (BM / TM) * (BN / TN);
    __shared__ float As[BK][BM + 4];
    __shared__ float Bs[BK][BN + 4];
    const int tid = threadIdx.x;
    const int tx = tid % (BN / TN);
    const int ty = tid / (BN / TN);
    const int rowBase = blockIdx.y * BM;
    const int colBase = blockIdx.x * BN;
    float acc[TM][TN];
    #pragma unroll
    for (int i = 0; i < TM; i++)
        #pragma unroll
        for (int j = 0; j < TN; j++) acc[i][j] = 0.f;
    for (int k0 = 0; k0 < K; k0 += BK) {
        for (int i = tid; i < BM * BK / 4; i += NT) {
            int r = i / (BK / 4), kq = i % (BK / 4);
            int gr = rowBase + r;
            float4 v = make_float4(0.f, 0.f, 0.f, 0.f);
            if (gr < M)
                v = *reinterpret_cast<const float4*>(A + (size_t)gr * K + k0 + kq * 4);
            As[kq * 4 + 0][r] = v.x;
            As[kq * 4 + 1][r] = v.y;
            As[kq * 4 + 2][r] = v.z;
            As[kq * 4 + 3][r] = v.w;
        }
        for (int i = tid; i < BK * BN / 4; i += NT) {
            int kk = i / (BN / 4), cq = i % (BN / 4);
            *reinterpret_cast<float4*>(&Bs[kk][cq * 4]) =
                *reinterpret_cast<const float4*>(B + (size_t)(k0 + kk) * Nn + colBase + cq * 4);
        }
        __syncthreads();
        #pragma unroll
        for (int kk = 0; kk < BK; kk++) {
            float a[TM], b[TN];
            #pragma unroll
            for (int i = 0; i < TM; i += 4) {
                float4 v = *reinterpret_cast<const float4*>(&As[kk][ty * TM + i]);
                a[i] = v.x; a[i + 1] = v.y; a[i + 2] = v.z; a[i + 3] = v.w;
            }
            #pragma unroll
            for (int j = 0; j < TN; j += 4) {
                float4 v = *reinterpret_cast<const float4*>(&Bs[kk][tx * TN + j]);
                b[j] = v.x; b[j + 1] = v.y; b[j + 2] = v.z; b[j + 3] = v.w;
            }
            #pragma unroll
            for (int i = 0; i < TM; i++)
                #pragma unroll
                for (int j = 0; j < TN; j++)
                    acc[i][j] = fmaf(a[i], b[j], acc[i][j]);
        }
        __syncthreads();
    }
    #pragma unroll
    for (int i = 0; i < TM; i++) {
        int gr = rowBase + ty * TM + i;
        if (gr < M) {
            #pragma unroll
            for (int j = 0; j < TN; j += 4) {
                float4 v = make_float4(acc[i][j], acc[i][j + 1], acc[i][j + 2], acc[i][j + 3]);
                *reinterpret_cast<float4*>(C + (size_t)gr * Nn + colBase + tx * TN + j) = v;
            }
        }
    }
}

// ==================== aggregation ====================
__device__ __forceinline__ void fma4(float4& a, const float4& v, float w) {
    a.x = fmaf(v.x, w, a.x);
    a.y = fmaf(v.y, w, a.y);
    a.z = fmaf(v.z, w, a.z);
    a.w = fmaf(v.w, w, a.w);
}
__device__ __forceinline__ float4 bnrelu4(float4 acc, float4 bb, float4 gg, float4 ee,
                                          float4 mm, float4 vv) {
    float4 o;
    o.x = fmaxf(0.f, (acc.x + bb.x - mm.x) * rsqrtf(vv.x + EPSV) * gg.x + ee.x);
    o.y = fmaxf(0.f, (acc.y + bb.y - mm.y) * rsqrtf(vv.y + EPSV) * gg.y + ee.y);
    o.z = fmaxf(0.f, (acc.z + bb.z - mm.z) * rsqrtf(vv.z + EPSV) * gg.z + ee.z);
    o.w = fmaxf(0.f, (acc.w + bb.w - mm.w) * rsqrtf(vv.w + EPSV) * gg.w + ee.w);
    return o;
}

__global__ void agg_f32(const float* __restrict__ hin, float* __restrict__ hout,
                        const float* __restrict__ bias, const float* __restrict__ gamma,
                        const float* __restrict__ beta, const float* __restrict__ mean,
                        const float* __restrict__ var) {
    int row = blockIdx.x * (blockDim.x >> 5) + (threadIdx.x >> 5);
    if (row >= N_NODES) return;
    int lane = threadIdx.x & 31;
    int beg = g_rowptr[row], end = g_rowptr[row + 1];
    float4 a0 = make_float4(0.f, 0.f, 0.f, 0.f), a1 = a0;
    for (int p = beg; p < end; p++) {
        int s = g_csrc[p];
        float w = g_cw[p];
        const float4* r = reinterpret_cast<const float4*>(hin + (size_t)s * HID);
        fma4(a0, r[lane], w);
        fma4(a1, r[lane + 32], w);
    }
    const float4* b4 = reinterpret_cast<const float4*>(bias);
    const float4* g4 = reinterpret_cast<const float4*>(gamma);
    const float4* be4 = reinterpret_cast<const float4*>(beta);
    const float4* m4 = reinterpret_cast<const float4*>(mean);
    const float4* v4 = reinterpret_cast<const float4*>(var);
    float4* outr = reinterpret_cast<float4*>(hout + (size_t)row * HID);
    #pragma unroll
    for (int h = 0; h < 2; h++) {
        int f = lane + 32 * h;
        outr[f] = bnrelu4(h ? a1 : a0, b4[f], g4[f], be4[f], m4[f], v4[f]);
    }
}

__global__ void agg_bf16(const float* __restrict__ hin,
                         __nv_bfloat16* __restrict__ ohi, __nv_bfloat16* __restrict__ olo,
                         const float* __restrict__ bias, const float* __restrict__ gamma,
                         const float* __restrict__ beta, const float* __restrict__ mean,
                         const float* __restrict__ var) {
    int row = blockIdx.x * (blockDim.x >> 5) + (threadIdx.x >> 5);
    if (row >= N_NODES) return;
    int lane = threadIdx.x & 31;
    int beg = g_rowptr[row], end = g_rowptr[row + 1];
    float4 a0 = make_float4(0.f, 0.f, 0.f, 0.f), a1 = a0;
    for (int p = beg; p < end; p++) {
        int s = g_csrc[p];
        float w = g_cw[p];
        const float4* r = reinterpret_cast<const float4*>(hin + (size_t)s * HID);
        fma4(a0, r[lane], w);
        fma4(a1, r[lane + 32], w);
    }
    const float4* b4 = reinterpret_cast<const float4*>(bias);
    const float4* g4 = reinterpret_cast<const float4*>(gamma);
    const float4* be4 = reinterpret_cast<const float4*>(beta);
    const float4* m4 = reinterpret_cast<const float4*>(mean);
    const float4* v4 = reinterpret_cast<const float4*>(var);
    uint2* hi2 = reinterpret_cast<uint2*>(ohi + (size_t)row * HID);
    uint2* lo2 = reinterpret_cast<uint2*>(olo + (size_t)row * HID);
    #pragma unroll
    for (int h = 0; h < 2; h++) {
        int f = lane + 32 * h;
        float4 o = bnrelu4(h ? a1 : a0, b4[f], g4[f], be4[f], m4[f], v4[f]);
        float h0, l0, h1, l1, h2, l2, h3, l3;
        split1(o.x, h0, l0); split1(o.y, h1, l1); split1(o.z, h2, l2); split1(o.w, h3, l3);
        uint2 hh, ll;
        hh.x = pack_bf2(h0, h1); hh.y = pack_bf2(h2, h3);
        ll.x = pack_bf2(l0, l1); ll.y = pack_bf2(l2, l3);
        hi2[f] = hh;
        lo2[f] = ll;
    }
}

__global__ void agg_out(const float* __restrict__ hin, float* __restrict__ hout,
                        const float* __restrict__ bias) {
    int row = blockIdx.x * (blockDim.x >> 5) + (threadIdx.x >> 5);
    if (row >= N_NODES) return;
    int lane = threadIdx.x & 31;
    int beg = g_rowptr[row], end = g_rowptr[row + 1];
    bool act = lane < (CLS / 4);
    float4 a = make_float4(0.f, 0.f, 0.f, 0.f);
    for (int p = beg; p < end; p++) {
        int s = g_csrc[p];
        float w = g_cw[p];
        if (act) {
            float4 v = reinterpret_cast<const float4*>(hin + (size_t)s * CLS)[lane];
            fma4(a, v, w);
        }
    }
    if (act) {
        float4 b = reinterpret_cast<const float4*>(bias)[lane];
        a.x += b.x; a.y += b.y; a.z += b.z; a.w += b.w;
        reinterpret_cast<float4*>(hout + (size_t)row * CLS)[lane] = a;
    }
}

// ==================== launch ====================
extern "C" void kernel_launch(void* const* d_in, const int* in_sizes, int n_in,
                              void* d_out, int out_size) {
    const float* x     = (const float*)d_in[0];
    const void*  ei    = (const void*)d_in[1];
    const float* W1    = (const float*)d_in[2];
    const float* b1    = (const float*)d_in[3];
    const float* W2    = (const float*)d_in[4];
    const float* b2    = (const float*)d_in[5];
    const float* W3    = (const float*)d_in[6];
    const float* b3    = (const float*)d_in[7];
    const float* gamma = (const float*)d_in[8];
    const float* beta  = (const float*)d_in[9];
    const float* mean  = (const float*)d_in[10];
    const float* var   = (const float*)d_in[11];
    float* out = (float*)d_out;

    float *pA, *pB, *pC;
    __nv_bfloat16 *pXhi, *pXlo, *pW1hi, *pW1lo, *pW2hi, *pW2lo;
    cudaGetSymbolAddress((void**)&pA, g_bufA);
    cudaGetSymbolAddress((void**)&pB, g_bufB);
    cudaGetSymbolAddress((void**)&pC, g_bufC);
    cudaGetSymbolAddress((void**)&pXhi, g_Xhi);
    cudaGetSymbolAddress((void**)&pXlo, g_Xlo);
    cudaGetSymbolAddress((void**)&pW1hi, g_W1hi);
    cudaGetSymbolAddress((void**)&pW1lo, g_W1lo);
    cudaGetSymbolAddress((void**)&pW2hi, g_W2hi);
    cudaGetSymbolAddress((void**)&pW2lo, g_W2lo);

    cudaFuncSetAttribute(gemm_mma, cudaFuncAttributeMaxDynamicSharedMemorySize, G_SMEM);

    // graph prep
    k_detect<<<1, 64>>>(ei);
    k_init<<<(N_NODES + 255) / 256, 256>>>();
    k_edges<<<(E_EDGES + 255) / 256, 256>>>(ei);
    k_inv<<<(N_NODES + 255) / 256, 256>>>();
    k_scan<<<1, 1024>>>();
    k_fill<<<(E_EDGES + N_NODES + 255) / 256, 256>>>();

    // splits
    {
        size_t tX = (size_t)N_NODES * FEAT / 4;
        k_cvtX<<<(int)((tX + 255) / 256), 256>>>(x, pXhi, pXlo);
        k_cvtW<<<(FEAT * HID + 255) / 256, 256>>>(W1, pW1hi, pW1lo, FEAT, HID);
        k_cvtW<<<(HID * HID + 255) / 256, 256>>>(W2, pW2hi, pW2lo, HID, HID);
    }

    const int NT = (N_NODES + 127) / 128;   // 391 row tiles
    dim3 gg(NT, 2);

    // layer 1: mma GEMM (K=512) -> bufA ; agg+BN+ReLU -> bf16 hi/lo
    gemm_mma<<<gg, 256, G_SMEM>>>(pXhi, pXlo, pW1hi, pW1lo, pA, N_NODES, FEAT);
    agg_bf16<<<(N_NODES + 7) / 8, 256>>>(pA, pXhi, pXlo, b1, gamma, beta, mean, var);

    // layer 2: mma GEMM (K=256) -> bufA ; agg+BN+ReLU -> fp32
    gemm_mma<<<gg, 256, G_SMEM>>>(pXhi, pXlo, pW2hi, pW2lo, pA, N_NODES, HID);
    agg_f32<<<(N_NODES + 7) / 8, 256>>>(pA, pB, b2, gamma, beta, mean, var);

    // layer 3: small fp32 sgemm -> bufC ; agg + b3 -> out
    {
        dim3 g(1, (N_NODES + 127) / 128);
        sgemm<128, 40, 16, 8, 4><<<g, 160>>>(pB, W3, pC, N_NODES, HID, CLS);
    }
    agg_out<<<(N_NODES + 7) / 8, 256>>>(pC, out, b3);
}

// round 12
// speedup vs baseline: 1.6292x; 1.0613x over previous
#include <cuda_runtime.h>
#include <cuda_bf16.h>
#include <cstdint>

#define N_NODES 50000
#define E_EDGES 800000
#define FEAT    512
#define HID     256
#define CLS     40
#define CLSP    64
#define EPSV    1e-5f

#define SWZ128(o) ((o) ^ (((o) >> 3) & 0x70))

// ==================== baseline PTX helpers (compute_103-safe) ====================
__device__ __forceinline__ uint32_t smem_u32(const void* p) {
    uint32_t a;
    asm("{ .reg .u64 t; cvta.to.shared.u64 t, %1; cvt.u32.u64 %0, t; }" : "=r"(a) : "l"(p));
    return a;
}
__device__ __forceinline__ void ldsm_x4(uint32_t& r0, uint32_t& r1, uint32_t& r2, uint32_t& r3,
                                        uint32_t addr) {
    asm volatile("ldmatrix.sync.aligned.m8n8.x4.shared.b16 {%0,%1,%2,%3}, [%4];"
                 : "=r"(r0), "=r"(r1), "=r"(r2), "=r"(r3) : "r"(addr));
}
__device__ __forceinline__ void mma_bf16(float* c, const uint32_t* a, const uint32_t* b) {
    asm volatile(
        "mma.sync.aligned.m16n8k16.row.col.f32.bf16.bf16.f32 "
        "{%0,%1,%2,%3}, {%4,%5,%6,%7}, {%8,%9}, {%0,%1,%2,%3};"
        : "+f"(c[0]), "+f"(c[1]), "+f"(c[2]), "+f"(c[3])
        : "r"(a[0]), "r"(a[1]), "r"(a[2]), "r"(a[3]), "r"(b[0]), "r"(b[1]));
}
__device__ __forceinline__ void cp_async16(uint32_t dst, const void* src) {
    asm volatile("cp.async.cg.shared.global [%0], [%1], 16;" :: "r"(dst), "l"(src) : "memory");
}
#define CP_COMMIT() asm volatile("cp.async.commit_group;" ::: "memory")
#define CP_WAIT2()  asm volatile("cp.async.wait_group 2;" ::: "memory")
#define CP_WAIT1()  asm volatile("cp.async.wait_group 1;" ::: "memory")
#define CP_WAIT0()  asm volatile("cp.async.wait_group 0;" ::: "memory")

// ==================== scratch (device globals) ====================
__device__ int   g_degi[N_NODES];
__device__ float g_inv[N_NODES];
__device__ int   g_src[E_EDGES];
__device__ int   g_dst[E_EDGES];
__device__ int   g_rowptr[N_NODES + 1];
__device__ int   g_fill[N_NODES];
__device__ int   g_csrc[E_EDGES + N_NODES];
__device__ float g_cw[E_EDGES + N_NODES];
__device__ int   g_is64;
__device__ float g_bufA[(size_t)N_NODES * HID];
__device__ float g_bufC[(size_t)N_NODES * CLSP];
__device__ __nv_bfloat16 g_Xhi[(size_t)N_NODES * FEAT];
__device__ __nv_bfloat16 g_Xlo[(size_t)N_NODES * FEAT];
__device__ __nv_bfloat16 g_W1hi[HID * FEAT];
__device__ __nv_bfloat16 g_W1lo[HID * FEAT];
__device__ __nv_bfloat16 g_W2hi[HID * HID];
__device__ __nv_bfloat16 g_W2lo[HID * HID];
__device__ __nv_bfloat16 g_W3hi[CLSP * HID];
__device__ __nv_bfloat16 g_W3lo[CLSP * HID];

// ==================== prep kernels ====================
// init degrees + detect edge dtype (warp 0 of block 0 samples 32 values)
__global__ void k_init(const void* eiraw) {
    int i = blockIdx.x * blockDim.x + threadIdx.x;
    if (i < N_NODES) g_degi[i] = 1;
    if (blockIdx.x == 0 && threadIdx.x < 32) {
        const long long* e64 = (const long long*)eiraw;
        long long v = e64[threadIdx.x];
        int ok = (v >= 0 && v < N_NODES) ? 1 : 0;
        unsigned m = __ballot_sync(0xffffffffu, ok);
        if (threadIdx.x == 0) g_is64 = (m == 0xffffffffu) ? 1 : 0;
    }
}
__device__ __forceinline__ int clampN(int v) {
    v = v < 0 ? 0 : v;
    return v >= N_NODES ? N_NODES - 1 : v;
}
__global__ void k_edges(const void* eiraw) {
    int e = blockIdx.x * blockDim.x + threadIdx.x;
    if (e >= E_EDGES) return;
    int s, d;
    if (g_is64) {
        const long long* p = (const long long*)eiraw;
        s = (int)p[e]; d = (int)p[E_EDGES + e];
    } else {
        const int* p = (const int*)eiraw;
        s = p[e]; d = p[E_EDGES + e];
    }
    s = clampN(s); d = clampN(d);
    g_src[e] = s; g_dst[e] = d;
    atomicAdd(&g_degi[d], 1);
}
// exclusive scan of degrees -> rowptr/fill; also writes inv-sqrt degrees
__global__ void k_scan() {
    __shared__ int wsum[32];
    __shared__ int carry_s;
    int tid = threadIdx.x, lane = tid & 31, wid = tid >> 5;
    if (tid == 0) carry_s = 0;
    __syncthreads();
    for (int start = 0; start < N_NODES; start += 1024) {
        int i = start + tid;
        int v = (i < N_NODES) ? g_degi[i] : 0;
        if (i < N_NODES) g_inv[i] = rsqrtf((float)v);
        int x = v;
        #pragma unroll
        for (int o = 1; o < 32; o <<= 1) {
            int t = __shfl_up_sync(0xffffffffu, x, o);
            if (lane >= o) x += t;
        }
        if (lane == 31) wsum[wid] = x;
        __syncthreads();
        if (wid == 0) {
            int s = wsum[lane];
            #pragma unroll
            for (int o = 1; o < 32; o <<= 1) {
                int t = __shfl_up_sync(0xffffffffu, s, o);
                if (lane >= o) s += t;
            }
            wsum[lane] = s;
        }
        __syncthreads();
        int excl = x - v + (wid ? wsum[wid - 1] : 0) + carry_s;
        if (i < N_NODES) { g_rowptr[i] = excl; g_fill[i] = excl; }
        int total = wsum[31];
        __syncthreads();
        if (tid == 0) carry_s += total;
        __syncthreads();
    }
    if (threadIdx.x == 0) g_rowptr[N_NODES] = carry_s;
}
__global__ void k_fill() {
    int idx = blockIdx.x * blockDim.x + threadIdx.x;
    if (idx >= E_EDGES + N_NODES) return;
    if (idx < E_EDGES) {
        int s = g_src[idx], d = g_dst[idx];
        int slot = atomicAdd(&g_fill[d], 1);
        g_csrc[slot] = s;
        g_cw[slot] = g_inv[s] * g_inv[d];
    } else {
        int i = idx - E_EDGES;
        int slot = atomicAdd(&g_fill[i], 1);
        g_csrc[slot] = i;
        float iv = g_inv[i];
        g_cw[slot] = iv * iv;
    }
}

// ==================== fp32 -> bf16 hi/lo split ====================
__device__ __forceinline__ uint32_t pack_bf2(float a, float b) {
    return (uint32_t)__bfloat16_as_ushort(__float2bfloat16_rn(a)) |
           ((uint32_t)__bfloat16_as_ushort(__float2bfloat16_rn(b)) << 16);
}
__device__ __forceinline__ void split1(float x, float& hi, float& lo) {
    __nv_bfloat16 h = __float2bfloat16_rn(x);
    hi = __bfloat162float(h);
    lo = x - hi;
}

__global__ void k_cvtX(const float* __restrict__ x,
                       __nv_bfloat16* __restrict__ ohi, __nv_bfloat16* __restrict__ olo) {
    size_t i = (size_t)blockIdx.x * blockDim.x + threadIdx.x;
    size_t total = (size_t)N_NODES * FEAT / 4;
    if (i >= total) return;
    float4 v = reinterpret_cast<const float4*>(x)[i];
    float h0, l0, h1, l1, h2, l2, h3, l3;
    split1(v.x, h0, l0); split1(v.y, h1, l1); split1(v.z, h2, l2); split1(v.w, h3, l3);
    uint2 hh, ll;
    hh.x = pack_bf2(h0, h1); hh.y = pack_bf2(h2, h3);
    ll.x = pack_bf2(l0, l1); ll.y = pack_bf2(l2, l3);
    reinterpret_cast<uint2*>(ohi)[i] = hh;
    reinterpret_cast<uint2*>(olo)[i] = ll;
}

// all three weights -> transposed hi/lo bf16, W3 padded to 64 output cols
#define W1_ELEMS (FEAT * HID)
#define W2_ELEMS (HID * HID)
#define W3_ELEMS (CLSP * HID)
__global__ void k_cvtWall(const float* __restrict__ W1, const float* __restrict__ W2,
                          const float* __restrict__ W3) {
    int i = blockIdx.x * blockDim.x + threadIdx.x;
    float h, l;
    if (i < W1_ELEMS) {
        int k = i / HID, n = i % HID;
        split1(W1[i], h, l);
        g_W1hi[(size_t)n * FEAT + k] = __float2bfloat16_rn(h);
        g_W1lo[(size_t)n * FEAT + k] = __float2bfloat16_rn(l);
    } else if (i < W1_ELEMS + W2_ELEMS) {
        int j = i - W1_ELEMS;
        int k = j / HID, n = j % HID;
        split1(W2[j], h, l);
        g_W2hi[(size_t)n * HID + k] = __float2bfloat16_rn(h);
        g_W2lo[(size_t)n * HID + k] = __float2bfloat16_rn(l);
    } else if (i < W1_ELEMS + W2_ELEMS + W3_ELEMS) {
        int j = i - W1_ELEMS - W2_ELEMS;
        int n = j / HID, k = j % HID;
        float v = (n < CLS) ? W3[k * CLS + n] : 0.f;
        split1(v, h, l);
        g_W3hi[(size_t)n * HID + k] = __float2bfloat16_rn(h);
        g_W3lo[(size_t)n * HID + k] = __float2bfloat16_rn(l);
    }
}

// ==================== mma.sync split-bf16 GEMM (templated N tile) ====================
// C[M x (grid.y*NCOLS)] = A[M x KTOT] * B^T, B stored [ncols x KTOT] n-major.
// CTA tile 128 x NCOLS, 8 warps, K-chunk 64, 3-stage cp.async.
#define KC 64
template<int NCOLS>
__global__ void __launch_bounds__(256, 1)
gemm_mma(const __nv_bfloat16* __restrict__ Ahi, const __nv_bfloat16* __restrict__ Alo,
         const __nv_bfloat16* __restrict__ Bhi, const __nv_bfloat16* __restrict__ Blo,
         float* __restrict__ C, int M, int KTOT, int ldc) {
    constexpr int WARP_N = NCOLS / 2;   // 64 or 32
    constexpr int NT8    = WARP_N / 8;  // 8 or 4
    constexpr int NG     = NT8 / 2;     // 4 or 2
    constexpr int AT     = 16384;       // 128 x 64 bf16
    constexpr int BT     = NCOLS * 128; // NCOLS x 64 bf16
    constexpr int STG    = 2 * AT + 2 * BT;

    extern __shared__ char sm[];
    const int tid = threadIdx.x, lane = tid & 31, wid = tid >> 5;
    const int rowBase = blockIdx.x * 128, colBase = blockIdx.y * NCOLS;
    const int wm = wid >> 1, wn = wid & 1;
    const int nch = KTOT / KC;

    auto issue = [&](int c) {
        int k0 = c * KC;
        char* base = sm + (c % 3) * STG;
        #pragma unroll
        for (int u = tid; u < 1024; u += 256) {
            int r = u >> 3, q = u & 7;
            int gr = rowBase + r;
            if (gr >= M) gr = M - 1;
            size_t ga = (size_t)gr * KTOT + k0 + q * 8;
            uint32_t off = SWZ128((r << 7) + (q << 4));
            cp_async16(smem_u32(base + off), Ahi + ga);
            cp_async16(smem_u32(base + AT + off), Alo + ga);
        }
        #pragma unroll
        for (int u = tid; u < NCOLS * 8; u += 256) {
            int nr = u >> 3, q = u & 7;
            size_t gb = (size_t)(colBase + nr) * KTOT + k0 + q * 8;
            uint32_t off = SWZ128((nr << 7) + (q << 4));
            cp_async16(smem_u32(base + 2 * AT + off), Bhi + gb);
            cp_async16(smem_u32(base + 2 * AT + BT + off), Blo + gb);
        }
        CP_COMMIT();
    };

    float acc[2][NT8][4];
    #pragma unroll
    for (int i = 0; i < 2; i++)
        #pragma unroll
        for (int j = 0; j < NT8; j++)
            #pragma unroll
            for (int k = 0; k < 4; k++) acc[i][j][k] = 0.f;

    issue(0);
    if (nch > 1) issue(1);
    if (nch > 2) issue(2);

    for (int c = 0; c < nch; c++) {
        int rem = nch - 1 - c;
        if (rem >= 2) { CP_WAIT2(); } else if (rem == 1) { CP_WAIT1(); } else { CP_WAIT0(); }
        __syncthreads();
        char* base = sm + (c % 3) * STG;
        uint32_t sA_hi = smem_u32(base);
        uint32_t sA_lo = sA_hi + AT;
        uint32_t sB_hi = sA_hi + 2 * AT;
        uint32_t sB_lo = sB_hi + BT;
        #pragma unroll
        for (int kk = 0; kk < 4; kk++) {
            uint32_t ah[2][4], al[2][4], bh[NT8][2], bl[NT8][2];
            #pragma unroll
            for (int mt = 0; mt < 2; mt++) {
                int row = wm * 32 + mt * 16 + (lane & 15);
                int q = kk * 2 + (lane >> 4);
                uint32_t off = SWZ128((row << 7) + (q << 4));
                ldsm_x4(ah[mt][0], ah[mt][1], ah[mt][2], ah[mt][3], sA_hi + off);
                ldsm_x4(al[mt][0], al[mt][1], al[mt][2], al[mt][3], sA_lo + off);
            }
            #pragma unroll
            for (int ng = 0; ng < NG; ng++) {
                int nr = wn * WARP_N + ng * 16 + ((lane >> 4) << 3) + (lane & 7);
                int q = kk * 2 + ((lane >> 3) & 1);
                uint32_t off = SWZ128((nr << 7) + (q << 4));
                uint32_t r0, r1, r2, r3;
                ldsm_x4(r0, r1, r2, r3, sB_hi + off);
                bh[ng * 2][0] = r0; bh[ng * 2][1] = r1;
                bh[ng * 2 + 1][0] = r2; bh[ng * 2 + 1][1] = r3;
                ldsm_x4(r0, r1, r2, r3, sB_lo + off);
                bl[ng * 2][0] = r0; bl[ng * 2][1] = r1;
                bl[ng * 2 + 1][0] = r2; bl[ng * 2 + 1][1] = r3;
            }
            #pragma unroll
            for (int mt = 0; mt < 2; mt++)
                #pragma unroll
                for (int nt = 0; nt < NT8; nt++) {
                    mma_bf16(acc[mt][nt], ah[mt], bh[nt]);
                    mma_bf16(acc[mt][nt], ah[mt], bl[nt]);
                    mma_bf16(acc[mt][nt], al[mt], bh[nt]);
                }
        }
        __syncthreads();
        if (c + 3 < nch) issue(c + 3);
    }

    #pragma unroll
    for (int mt = 0; mt < 2; mt++) {
        int row0 = rowBase + wm * 32 + mt * 16 + (lane >> 2);
        #pragma unroll
        for (int nt = 0; nt < NT8; nt++) {
            int cc = colBase + wn * WARP_N + nt * 8 + 2 * (lane & 3);
            if (row0 < M)
                *reinterpret_cast<float2*>(C + (size_t)row0 * ldc + cc) =
                    make_float2(acc[mt][nt][0], acc[mt][nt][1]);
            if (row0 + 8 < M)
                *reinterpret_cast<float2*>(C + (size_t)(row0 + 8) * ldc + cc) =
                    make_float2(acc[mt][nt][2], acc[mt][nt][3]);
        }
    }
}

// ==================== aggregation ====================
__device__ __forceinline__ void fma4(float4& a, const float4& v, float w) {
    a.x = fmaf(v.x, w, a.x);
    a.y = fmaf(v.y, w, a.y);
    a.z = fmaf(v.z, w, a.z);
    a.w = fmaf(v.w, w, a.w);
}
__device__ __forceinline__ float4 bnrelu4(float4 acc, float4 bb, float4 gg, float4 ee,
                                          float4 mm, float4 vv) {
    float4 o;
    o.x = fmaxf(0.f, (acc.x + bb.x - mm.x) * rsqrtf(vv.x + EPSV) * gg.x + ee.x);
    o.y = fmaxf(0.f, (acc.y + bb.y - mm.y) * rsqrtf(vv.y + EPSV) * gg.y + ee.y);
    o.z = fmaxf(0.f, (acc.z + bb.z - mm.z) * rsqrtf(vv.z + EPSV) * gg.z + ee.z);
    o.w = fmaxf(0.f, (acc.w + bb.w - mm.w) * rsqrtf(vv.w + EPSV) * gg.w + ee.w);
    return o;
}

// CSR agg + bias + BN + ReLU -> bf16 hi/lo (feeds next mma GEMM)
__global__ void agg_bf16(const float* __restrict__ hin,
                         __nv_bfloat16* __restrict__ ohi, __nv_bfloat16* __restrict__ olo,
                         const float* __restrict__ bias, const float* __restrict__ gamma,
                         const float* __restrict__ beta, const float* __restrict__ mean,
                         const float* __restrict__ var) {
    int row = blockIdx.x * (blockDim.x >> 5) + (threadIdx.x >> 5);
    if (row >= N_NODES) return;
    int lane = threadIdx.x & 31;
    int beg = g_rowptr[row], end = g_rowptr[row + 1];
    float4 a0 = make_float4(0.f, 0.f, 0.f, 0.f), a1 = a0;
    for (int p = beg; p < end; p++) {
        int s = g_csrc[p];
        float w = g_cw[p];
        const float4* r = reinterpret_cast<const float4*>(hin + (size_t)s * HID);
        fma4(a0, r[lane], w);
        fma4(a1, r[lane + 32], w);
    }
    const float4* b4 = reinterpret_cast<const float4*>(bias);
    const float4* g4 = reinterpret_cast<const float4*>(gamma);
    const float4* be4 = reinterpret_cast<const float4*>(beta);
    const float4* m4 = reinterpret_cast<const float4*>(mean);
    const float4* v4 = reinterpret_cast<const float4*>(var);
    uint2* hi2 = reinterpret_cast<uint2*>(ohi + (size_t)row * HID);
    uint2* lo2 = reinterpret_cast<uint2*>(olo + (size_t)row * HID);
    #pragma unroll
    for (int h = 0; h < 2; h++) {
        int f = lane + 32 * h;
        float4 o = bnrelu4(h ? a1 : a0, b4[f], g4[f], be4[f], m4[f], v4[f]);
        float h0, l0, h1, l1, h2, l2, h3, l3;
        split1(o.x, h0, l0); split1(o.y, h1, l1); split1(o.z, h2, l2); split1(o.w, h3, l3);
        uint2 hh, ll;
        hh.x = pack_bf2(h0, h1); hh.y = pack_bf2(h2, h3);
        ll.x = pack_bf2(l0, l1); ll.y = pack_bf2(l2, l3);
        hi2[f] = hh;
        lo2[f] = ll;
    }
}

// final aggregation + bias: reads padded 64-wide logits, writes 40-wide output
__global__ void agg_out(const float* __restrict__ hin, float* __restrict__ hout,
                        const float* __restrict__ bias) {
    int row = blockIdx.x * (blockDim.x >> 5) + (threadIdx.x >> 5);
    if (row >= N_NODES) return;
    int lane = threadIdx.x & 31;
    int beg = g_rowptr[row], end = g_rowptr[row + 1];
    bool act = lane < (CLS / 4);
    float4 a = make_float4(0.f, 0.f, 0.f, 0.f);
    for (int p = beg; p < end; p++) {
        int s = g_csrc[p];
        float w = g_cw[p];
        if (act) {
            float4 v = reinterpret_cast<const float4*>(hin + (size_t)s * CLSP)[lane];
            fma4(a, v, w);
        }
    }
    if (act) {
        float4 b = reinterpret_cast<const float4*>(bias)[lane];
        a.x += b.x; a.y += b.y; a.z += b.z; a.w += b.w;
        reinterpret_cast<float4*>(hout + (size_t)row * CLS)[lane] = a;
    }
}

// ==================== launch ====================
extern "C" void kernel_launch(void* const* d_in, const int* in_sizes, int n_in,
                              void* d_out, int out_size) {
    const float* x     = (const float*)d_in[0];
    const void*  ei    = (const void*)d_in[1];
    const float* W1    = (const float*)d_in[2];
    const float* b1    = (const float*)d_in[3];
    const float* W2    = (const float*)d_in[4];
    const float* b2    = (const float*)d_in[5];
    const float* W3    = (const float*)d_in[6];
    const float* b3    = (const float*)d_in[7];
    const float* gamma = (const float*)d_in[8];
    const float* beta  = (const float*)d_in[9];
    const float* mean  = (const float*)d_in[10];
    const float* var   = (const float*)d_in[11];
    float* out = (float*)d_out;

    float *pA, *pC;
    __nv_bfloat16 *pXhi, *pXlo, *pW1hi, *pW1lo, *pW2hi, *pW2lo, *pW3hi, *pW3lo;
    cudaGetSymbolAddress((void**)&pA, g_bufA);
    cudaGetSymbolAddress((void**)&pC, g_bufC);
    cudaGetSymbolAddress((void**)&pXhi, g_Xhi);
    cudaGetSymbolAddress((void**)&pXlo, g_Xlo);
    cudaGetSymbolAddress((void**)&pW1hi, g_W1hi);
    cudaGetSymbolAddress((void**)&pW1lo, g_W1lo);
    cudaGetSymbolAddress((void**)&pW2hi, g_W2hi);
    cudaGetSymbolAddress((void**)&pW2lo, g_W2lo);
    cudaGetSymbolAddress((void**)&pW3hi, g_W3hi);
    cudaGetSymbolAddress((void**)&pW3lo, g_W3lo);

    constexpr int SM128 = 3 * (2 * 16384 + 2 * 128 * 128);  // 196608
    constexpr int SM64  = 3 * (2 * 16384 + 2 * 64 * 128);   // 147456
    cudaFuncSetAttribute(gemm_mma<128>, cudaFuncAttributeMaxDynamicSharedMemorySize, SM128);
    cudaFuncSetAttribute(gemm_mma<64>, cudaFuncAttributeMaxDynamicSharedMemorySize, SM64);

    // graph prep (4 launches)
    k_init<<<(N_NODES + 255) / 256, 256>>>(ei);
    k_edges<<<(E_EDGES + 255) / 256, 256>>>(ei);
    k_scan<<<1, 1024>>>();
    k_fill<<<(E_EDGES + N_NODES + 255) / 256, 256>>>();

    // conversions (2 launches)
    {
        size_t tX = (size_t)N_NODES * FEAT / 4;
        k_cvtX<<<(int)((tX + 255) / 256), 256>>>(x, pXhi, pXlo);
        int tW = W1_ELEMS + W2_ELEMS + W3_ELEMS;
        k_cvtWall<<<(tW + 255) / 256, 256>>>(W1, W2, W3);
    }

    const int NT = (N_NODES + 127) / 128;   // 391 row tiles

    // layer 1: mma GEMM (K=512) -> bufA ; agg+BN+ReLU -> bf16 hi/lo
    gemm_mma<128><<<dim3(NT, 2), 256, SM128>>>(pXhi, pXlo, pW1hi, pW1lo, pA, N_NODES, FEAT, HID);
    agg_bf16<<<(N_NODES + 7) / 8, 256>>>(pA, pXhi, pXlo, b1, gamma, beta, mean, var);

    // layer 2: mma GEMM (K=256) -> bufA ; agg+BN+ReLU -> bf16 hi/lo
    gemm_mma<128><<<dim3(NT, 2), 256, SM128>>>(pXhi, pXlo, pW2hi, pW2lo, pA, N_NODES, HID, HID);
    agg_bf16<<<(N_NODES + 7) / 8, 256>>>(pA, pXhi, pXlo, b2, gamma, beta, mean, var);

    // layer 3: mma GEMM (K=256, padded N=64) -> bufC ; agg + b3 -> out
    gemm_mma<64><<<dim3(NT, 1), 256, SM64>>>(pXhi, pXlo, pW3hi, pW3lo, pC, N_NODES, HID, CLSP);
    agg_out<<<(N_NODES + 7) / 8, 256>>>(pC, out, b3);
}

// round 17
// speedup vs baseline: 1.6984x; 1.0425x over previous
#include <cuda_runtime.h>
#include <cuda_bf16.h>
#include <cuda_fp16.h>
#include <cstdint>

#define N_NODES 50000
#define E_EDGES 800000
#define FEAT    512
#define HID     256
#define CLS     40
#define CLSP    64
#define EPSV    1e-5f

#define SWZ128(o) ((o) ^ (((o) >> 3) & 0x70))

// ==================== baseline PTX helpers (compute_103-safe) ====================
__device__ __forceinline__ uint32_t smem_u32(const void* p) {
    uint32_t a;
    asm("{ .reg .u64 t; cvta.to.shared.u64 t, %1; cvt.u32.u64 %0, t; }" : "=r"(a) : "l"(p));
    return a;
}
__device__ __forceinline__ void ldsm_x4(uint32_t& r0, uint32_t& r1, uint32_t& r2, uint32_t& r3,
                                        uint32_t addr) {
    asm volatile("ldmatrix.sync.aligned.m8n8.x4.shared.b16 {%0,%1,%2,%3}, [%4];"
                 : "=r"(r0), "=r"(r1), "=r"(r2), "=r"(r3) : "r"(addr));
}
__device__ __forceinline__ void mma_bf16(float* c, const uint32_t* a, const uint32_t* b) {
    asm volatile(
        "mma.sync.aligned.m16n8k16.row.col.f32.bf16.bf16.f32 "
        "{%0,%1,%2,%3}, {%4,%5,%6,%7}, {%8,%9}, {%0,%1,%2,%3};"
        : "+f"(c[0]), "+f"(c[1]), "+f"(c[2]), "+f"(c[3])
        : "r"(a[0]), "r"(a[1]), "r"(a[2]), "r"(a[3]), "r"(b[0]), "r"(b[1]));
}
__device__ __forceinline__ void cp_async16(uint32_t dst, const void* src) {
    asm volatile("cp.async.cg.shared.global [%0], [%1], 16;" :: "r"(dst), "l"(src) : "memory");
}
#define CP_COMMIT() asm volatile("cp.async.commit_group;" ::: "memory")
#define CP_WAIT2()  asm volatile("cp.async.wait_group 2;" ::: "memory")
#define CP_WAIT1()  asm volatile("cp.async.wait_group 1;" ::: "memory")
#define CP_WAIT0()  asm volatile("cp.async.wait_group 0;" ::: "memory")

// ==================== scratch (device globals) ====================
__device__ int   g_degi[N_NODES];
__device__ float g_inv[N_NODES];
__device__ int   g_src[E_EDGES];
__device__ int   g_dst[E_EDGES];
__device__ int   g_rowptr[N_NODES + 1];
__device__ int   g_fill[N_NODES];
__device__ int   g_csrc[E_EDGES + N_NODES];
__device__ float g_cw[E_EDGES + N_NODES];
__device__ int   g_is64;
__device__ __half g_bufH[(size_t)N_NODES * HID];   // fp16 GEMM outputs (25.6 MB)
__device__ float  g_bufC[(size_t)N_NODES * CLSP];
__device__ __nv_bfloat16 g_Xhi[(size_t)N_NODES * FEAT];
__device__ __nv_bfloat16 g_Xlo[(size_t)N_NODES * FEAT];
__device__ __nv_bfloat16 g_W1hi[HID * FEAT];
__device__ __nv_bfloat16 g_W1lo[HID * FEAT];
__device__ __nv_bfloat16 g_W2hi[HID * HID];
__device__ __nv_bfloat16 g_W2lo[HID * HID];
__device__ __nv_bfloat16 g_W3hi[CLSP * HID];
__device__ __nv_bfloat16 g_W3lo[CLSP * HID];

// ==================== prep kernels ====================
__global__ void k_init(const void* eiraw) {
    int i = blockIdx.x * blockDim.x + threadIdx.x;
    if (i < N_NODES) g_degi[i] = 1;
    if (blockIdx.x == 0 && threadIdx.x < 32) {
        const long long* e64 = (const long long*)eiraw;
        long long v = e64[threadIdx.x];
        int ok = (v >= 0 && v < N_NODES) ? 1 : 0;
        unsigned m = __ballot_sync(0xffffffffu, ok);
        if (threadIdx.x == 0) g_is64 = (m == 0xffffffffu) ? 1 : 0;
    }
}
__device__ __forceinline__ int clampN(int v) {
    v = v < 0 ? 0 : v;
    return v >= N_NODES ? N_NODES - 1 : v;
}
__global__ void k_edges(const void* eiraw) {
    int e = blockIdx.x * blockDim.x + threadIdx.x;
    if (e >= E_EDGES) return;
    int s, d;
    if (g_is64) {
        const long long* p = (const long long*)eiraw;
        s = (int)p[e]; d = (int)p[E_EDGES + e];
    } else {
        const int* p = (const int*)eiraw;
        s = p[e]; d = p[E_EDGES + e];
    }
    s = clampN(s); d = clampN(d);
    g_src[e] = s; g_dst[e] = d;
    atomicAdd(&g_degi[d], 1);
}
__global__ void k_scan() {
    __shared__ int wsum[32];
    __shared__ int carry_s;
    int tid = threadIdx.x, lane = tid & 31, wid = tid >> 5;
    if (tid == 0) carry_s = 0;
    __syncthreads();
    for (int start = 0; start < N_NODES; start += 1024) {
        int i = start + tid;
        int v = (i < N_NODES) ? g_degi[i] : 0;
        if (i < N_NODES) g_inv[i] = rsqrtf((float)v);
        int x = v;
        #pragma unroll
        for (int o = 1; o < 32; o <<= 1) {
            int t = __shfl_up_sync(0xffffffffu, x, o);
            if (lane >= o) x += t;
        }
        if (lane == 31) wsum[wid] = x;
        __syncthreads();
        if (wid == 0) {
            int s = wsum[lane];
            #pragma unroll
            for (int o = 1; o < 32; o <<= 1) {
                int t = __shfl_up_sync(0xffffffffu, s, o);
                if (lane >= o) s += t;
            }
            wsum[lane] = s;
        }
        __syncthreads();
        int excl = x - v + (wid ? wsum[wid - 1] : 0) + carry_s;
        if (i < N_NODES) { g_rowptr[i] = excl; g_fill[i] = excl; }
        int total = wsum[31];
        __syncthreads();
        if (tid == 0) carry_s += total;
        __syncthreads();
    }
    if (threadIdx.x == 0) g_rowptr[N_NODES] = carry_s;
}
__global__ void k_fill() {
    int idx = blockIdx.x * blockDim.x + threadIdx.x;
    if (idx >= E_EDGES + N_NODES) return;
    if (idx < E_EDGES) {
        int s = g_src[idx], d = g_dst[idx];
        int slot = atomicAdd(&g_fill[d], 1);
        g_csrc[slot] = s;
        g_cw[slot] = g_inv[s] * g_inv[d];
    } else {
        int i = idx - E_EDGES;
        int slot = atomicAdd(&g_fill[i], 1);
        g_csrc[slot] = i;
        float iv = g_inv[i];
        g_cw[slot] = iv * iv;
    }
}

// ==================== fp32 -> bf16 hi/lo split ====================
__device__ __forceinline__ uint32_t pack_bf2(float a, float b) {
    return (uint32_t)__bfloat16_as_ushort(__float2bfloat16_rn(a)) |
           ((uint32_t)__bfloat16_as_ushort(__float2bfloat16_rn(b)) << 16);
}
__device__ __forceinline__ void split1(float x, float& hi, float& lo) {
    __nv_bfloat16 h = __float2bfloat16_rn(x);
    hi = __bfloat162float(h);
    lo = x - hi;
}

__global__ void k_cvtX(const float* __restrict__ x,
                       __nv_bfloat16* __restrict__ ohi, __nv_bfloat16* __restrict__ olo) {
    size_t i = (size_t)blockIdx.x * blockDim.x + threadIdx.x;
    size_t total = (size_t)N_NODES * FEAT / 4;
    if (i >= total) return;
    float4 v = reinterpret_cast<const float4*>(x)[i];
    float h0, l0, h1, l1, h2, l2, h3, l3;
    split1(v.x, h0, l0); split1(v.y, h1, l1); split1(v.z, h2, l2); split1(v.w, h3, l3);
    uint2 hh, ll;
    hh.x = pack_bf2(h0, h1); hh.y = pack_bf2(h2, h3);
    ll.x = pack_bf2(l0, l1); ll.y = pack_bf2(l2, l3);
    reinterpret_cast<uint2*>(ohi)[i] = hh;
    reinterpret_cast<uint2*>(olo)[i] = ll;
}

#define W1_ELEMS (FEAT * HID)
#define W2_ELEMS (HID * HID)
#define W3_ELEMS (CLSP * HID)
__global__ void k_cvtWall(const float* __restrict__ W1, const float* __restrict__ W2,
                          const float* __restrict__ W3) {
    int i = blockIdx.x * blockDim.x + threadIdx.x;
    float h, l;
    if (i < W1_ELEMS) {
        int k = i / HID, n = i % HID;
        split1(W1[i], h, l);
        g_W1hi[(size_t)n * FEAT + k] = __float2bfloat16_rn(h);
        g_W1lo[(size_t)n * FEAT + k] = __float2bfloat16_rn(l);
    } else if (i < W1_ELEMS + W2_ELEMS) {
        int j = i - W1_ELEMS;
        int k = j / HID, n = j % HID;
        split1(W2[j], h, l);
        g_W2hi[(size_t)n * HID + k] = __float2bfloat16_rn(h);
        g_W2lo[(size_t)n * HID + k] = __float2bfloat16_rn(l);
    } else if (i < W1_ELEMS + W2_ELEMS + W3_ELEMS) {
        int j = i - W1_ELEMS - W2_ELEMS;
        int n = j / HID, k = j % HID;
        float v = (n < CLS) ? W3[k * CLS + n] : 0.f;
        split1(v, h, l);
        g_W3hi[(size_t)n * HID + k] = __float2bfloat16_rn(h);
        g_W3lo[(size_t)n * HID + k] = __float2bfloat16_rn(l);
    }
}

// ==================== mma.sync split-bf16 GEMM ====================
// CTA tile 128 x NCOLS, 8 warps, K-chunk 64, 3-stage cp.async.
// HOUT: write fp16 output (halves epilogue + downstream agg traffic).
#define KC 64
template<int NCOLS, bool HOUT>
__global__ void __launch_bounds__(256, 1)
gemm_mma(const __nv_bfloat16* __restrict__ Ahi, const __nv_bfloat16* __restrict__ Alo,
         const __nv_bfloat16* __restrict__ Bhi, const __nv_bfloat16* __restrict__ Blo,
         void* __restrict__ C, int M, int KTOT, int ldc) {
    constexpr int WARP_N = NCOLS / 2;
    constexpr int NT8    = WARP_N / 8;
    constexpr int NG     = NT8 / 2;
    constexpr int AT     = 16384;
    constexpr int BT     = NCOLS * 128;
    constexpr int STG    = 2 * AT + 2 * BT;

    extern __shared__ char sm[];
    const int tid = threadIdx.x, lane = tid & 31, wid = tid >> 5;
    const int rowBase = blockIdx.x * 128, colBase = blockIdx.y * NCOLS;
    const int wm = wid >> 1, wn = wid & 1;
    const int nch = KTOT / KC;

    auto issue = [&](int c) {
        int k0 = c * KC;
        char* base = sm + (c % 3) * STG;
        #pragma unroll
        for (int u = tid; u < 1024; u += 256) {
            int r = u >> 3, q = u & 7;
            int gr = rowBase + r;
            if (gr >= M) gr = M - 1;
            size_t ga = (size_t)gr * KTOT + k0 + q * 8;
            uint32_t off = SWZ128((r << 7) + (q << 4));
            cp_async16(smem_u32(base + off), Ahi + ga);
            cp_async16(smem_u32(base + AT + off), Alo + ga);
        }
        #pragma unroll
        for (int u = tid; u < NCOLS * 8; u += 256) {
            int nr = u >> 3, q = u & 7;
            size_t gb = (size_t)(colBase + nr) * KTOT + k0 + q * 8;
            uint32_t off = SWZ128((nr << 7) + (q << 4));
            cp_async16(smem_u32(base + 2 * AT + off), Bhi + gb);
            cp_async16(smem_u32(base + 2 * AT + BT + off), Blo + gb);
        }
        CP_COMMIT();
    };

    float acc[2][NT8][4];
    #pragma unroll
    for (int i = 0; i < 2; i++)
        #pragma unroll
        for (int j = 0; j < NT8; j++)
            #pragma unroll
            for (int k = 0; k < 4; k++) acc[i][j][k] = 0.f;

    issue(0);
    if (nch > 1) issue(1);
    if (nch > 2) issue(2);

    for (int c = 0; c < nch; c++) {
        int rem = nch - 1 - c;
        if (rem >= 2) { CP_WAIT2(); } else if (rem == 1) { CP_WAIT1(); } else { CP_WAIT0(); }
        __syncthreads();
        char* base = sm + (c % 3) * STG;
        uint32_t sA_hi = smem_u32(base);
        uint32_t sA_lo = sA_hi + AT;
        uint32_t sB_hi = sA_hi + 2 * AT;
        uint32_t sB_lo = sB_hi + BT;
        #pragma unroll
        for (int kk = 0; kk < 4; kk++) {
            uint32_t ah[2][4], al[2][4], bh[NT8][2], bl[NT8][2];
            #pragma unroll
            for (int mt = 0; mt < 2; mt++) {
                int row = wm * 32 + mt * 16 + (lane & 15);
                int q = kk * 2 + (lane >> 4);
                uint32_t off = SWZ128((row << 7) + (q << 4));
                ldsm_x4(ah[mt][0], ah[mt][1], ah[mt][2], ah[mt][3], sA_hi + off);
                ldsm_x4(al[mt][0], al[mt][1], al[mt][2], al[mt][3], sA_lo + off);
            }
            #pragma unroll
            for (int ng = 0; ng < NG; ng++) {
                int nr = wn * WARP_N + ng * 16 + ((lane >> 4) << 3) + (lane & 7);
                int q = kk * 2 + ((lane >> 3) & 1);
                uint32_t off = SWZ128((nr << 7) + (q << 4));
                uint32_t r0, r1, r2, r3;
                ldsm_x4(r0, r1, r2, r3, sB_hi + off);
                bh[ng * 2][0] = r0; bh[ng * 2][1] = r1;
                bh[ng * 2 + 1][0] = r2; bh[ng * 2 + 1][1] = r3;
                ldsm_x4(r0, r1, r2, r3, sB_lo + off);
                bl[ng * 2][0] = r0; bl[ng * 2][1] = r1;
                bl[ng * 2 + 1][0] = r2; bl[ng * 2 + 1][1] = r3;
            }
            #pragma unroll
            for (int mt = 0; mt < 2; mt++)
                #pragma unroll
                for (int nt = 0; nt < NT8; nt++) {
                    mma_bf16(acc[mt][nt], ah[mt], bh[nt]);
                    mma_bf16(acc[mt][nt], ah[mt], bl[nt]);
                    mma_bf16(acc[mt][nt], al[mt], bh[nt]);
                }
        }
        __syncthreads();
        if (c + 3 < nch) issue(c + 3);
    }

    #pragma unroll
    for (int mt = 0; mt < 2; mt++) {
        int row0 = rowBase + wm * 32 + mt * 16 + (lane >> 2);
        #pragma unroll
        for (int nt = 0; nt < NT8; nt++) {
            int cc = colBase + wn * WARP_N + nt * 8 + 2 * (lane & 3);
            if (HOUT) {
                __half* Ch = (__half*)C;
                if (row0 < M)
                    *reinterpret_cast<__half2*>(Ch + (size_t)row0 * ldc + cc) =
                        __floats2half2_rn(acc[mt][nt][0], acc[mt][nt][1]);
                if (row0 + 8 < M)
                    *reinterpret_cast<__half2*>(Ch + (size_t)(row0 + 8) * ldc + cc) =
                        __floats2half2_rn(acc[mt][nt][2], acc[mt][nt][3]);
            } else {
                float* Cf = (float*)C;
                if (row0 < M)
                    *reinterpret_cast<float2*>(Cf + (size_t)row0 * ldc + cc) =
                        make_float2(acc[mt][nt][0], acc[mt][nt][1]);
                if (row0 + 8 < M)
                    *reinterpret_cast<float2*>(Cf + (size_t)(row0 + 8) * ldc + cc) =
                        make_float2(acc[mt][nt][2], acc[mt][nt][3]);
            }
        }
    }
}

// ==================== aggregation ====================
__device__ __forceinline__ float4 bnrelu4(float4 acc, float4 bb, float4 gg, float4 ee,
                                          float4 mm, float4 vv) {
    float4 o;
    o.x = fmaxf(0.f, (acc.x + bb.x - mm.x) * rsqrtf(vv.x + EPSV) * gg.x + ee.x);
    o.y = fmaxf(0.f, (acc.y + bb.y - mm.y) * rsqrtf(vv.y + EPSV) * gg.y + ee.y);
    o.z = fmaxf(0.f, (acc.z + bb.z - mm.z) * rsqrtf(vv.z + EPSV) * gg.z + ee.z);
    o.w = fmaxf(0.f, (acc.w + bb.w - mm.w) * rsqrtf(vv.w + EPSV) * gg.w + ee.w);
    return o;
}
__device__ __forceinline__ void fma4(float4& a, const float4& v, float w) {
    a.x = fmaf(v.x, w, a.x);
    a.y = fmaf(v.y, w, a.y);
    a.z = fmaf(v.z, w, a.z);
    a.w = fmaf(v.w, w, a.w);
}

// CSR agg (fp16 features) + bias + BN + ReLU -> bf16 hi/lo (feeds next mma GEMM)
// Each lane owns 8 contiguous features: one uint4 (8 halves) per row-visit.
__global__ void agg_h2b(const __half* __restrict__ hin,
                        __nv_bfloat16* __restrict__ ohi, __nv_bfloat16* __restrict__ olo,
                        const float* __restrict__ bias, const float* __restrict__ gamma,
                        const float* __restrict__ beta, const float* __restrict__ mean,
                        const float* __restrict__ var) {
    int row = blockIdx.x * (blockDim.x >> 5) + (threadIdx.x >> 5);
    if (row >= N_NODES) return;
    int lane = threadIdx.x & 31;
    int beg = g_rowptr[row], end = g_rowptr[row + 1];
    float4 a0 = make_float4(0.f, 0.f, 0.f, 0.f), a1 = a0;
    for (int p = beg; p < end; p++) {
        int s = g_csrc[p];
        float w = g_cw[p];
        uint4 v = reinterpret_cast<const uint4*>(hin + (size_t)s * HID)[lane];
        float2 f0 = __half22float2(*reinterpret_cast<__half2*>(&v.x));
        float2 f1 = __half22float2(*reinterpret_cast<__half2*>(&v.y));
        float2 f2 = __half22float2(*reinterpret_cast<__half2*>(&v.z));
        float2 f3 = __half22float2(*reinterpret_cast<__half2*>(&v.w));
        a0.x = fmaf(f0.x, w, a0.x); a0.y = fmaf(f0.y, w, a0.y);
        a0.z = fmaf(f1.x, w, a0.z); a0.w = fmaf(f1.y, w, a0.w);
        a1.x = fmaf(f2.x, w, a1.x); a1.y = fmaf(f2.y, w, a1.y);
        a1.z = fmaf(f3.x, w, a1.z); a1.w = fmaf(f3.y, w, a1.w);
    }
    const float4* b4 = reinterpret_cast<const float4*>(bias);
    const float4* g4 = reinterpret_cast<const float4*>(gamma);
    const float4* be4 = reinterpret_cast<const float4*>(beta);
    const float4* m4 = reinterpret_cast<const float4*>(mean);
    const float4* v4 = reinterpret_cast<const float4*>(var);
    int f0i = 2 * lane, f1i = 2 * lane + 1;
    float4 o0 = bnrelu4(a0, b4[f0i], g4[f0i], be4[f0i], m4[f0i], v4[f0i]);
    float4 o1 = bnrelu4(a1, b4[f1i], g4[f1i], be4[f1i], m4[f1i], v4[f1i]);
    float h0, l0, h1, l1, h2, l2, h3, l3, h4, l4, h5, l5, h6, l6, h7, l7;
    split1(o0.x, h0, l0); split1(o0.y, h1, l1); split1(o0.z, h2, l2); split1(o0.w, h3, l3);
    split1(o1.x, h4, l4); split1(o1.y, h5, l5); split1(o1.z, h6, l6); split1(o1.w, h7, l7);
    uint4 hh, ll;
    hh.x = pack_bf2(h0, h1); hh.y = pack_bf2(h2, h3);
    hh.z = pack_bf2(h4, h5); hh.w = pack_bf2(h6, h7);
    ll.x = pack_bf2(l0, l1); ll.y = pack_bf2(l2, l3);
    ll.z = pack_bf2(l4, l5); ll.w = pack_bf2(l6, l7);
    reinterpret_cast<uint4*>(ohi + (size_t)row * HID)[lane] = hh;
    reinterpret_cast<uint4*>(olo + (size_t)row * HID)[lane] = ll;
}

// final aggregation + bias: reads padded 64-wide fp32 logits, writes 40-wide output
__global__ void agg_out(const float* __restrict__ hin, float* __restrict__ hout,
                        const float* __restrict__ bias) {
    int row = blockIdx.x * (blockDim.x >> 5) + (threadIdx.x >> 5);
    if (row >= N_NODES) return;
    int lane = threadIdx.x & 31;
    int beg = g_rowptr[row], end = g_rowptr[row + 1];
    bool act = lane < (CLS / 4);
    float4 a = make_float4(0.f, 0.f, 0.f, 0.f);
    for (int p = beg; p < end; p++) {
        int s = g_csrc[p];
        float w = g_cw[p];
        if (act) {
            float4 v = reinterpret_cast<const float4*>(hin + (size_t)s * CLSP)[lane];
            fma4(a, v, w);
        }
    }
    if (act) {
        float4 b = reinterpret_cast<const float4*>(bias)[lane];
        a.x += b.x; a.y += b.y; a.z += b.z; a.w += b.w;
        reinterpret_cast<float4*>(hout + (size_t)row * CLS)[lane] = a;
    }
}

// ==================== launch ====================
extern "C" void kernel_launch(void* const* d_in, const int* in_sizes, int n_in,
                              void* d_out, int out_size) {
    const float* x     = (const float*)d_in[0];
    const void*  ei    = (const void*)d_in[1];
    const float* W1    = (const float*)d_in[2];
    const float* b1    = (const float*)d_in[3];
    const float* W2    = (const float*)d_in[4];
    const float* b2    = (const float*)d_in[5];
    const float* W3    = (const float*)d_in[6];
    const float* b3    = (const float*)d_in[7];
    const float* gamma = (const float*)d_in[8];
    const float* beta  = (const float*)d_in[9];
    const float* mean  = (const float*)d_in[10];
    const float* var   = (const float*)d_in[11];
    float* out = (float*)d_out;

    __half* pH;
    float* pC;
    __nv_bfloat16 *pXhi, *pXlo, *pW1hi, *pW1lo, *pW2hi, *pW2lo, *pW3hi, *pW3lo;
    cudaGetSymbolAddress((void**)&pH, g_bufH);
    cudaGetSymbolAddress((void**)&pC, g_bufC);
    cudaGetSymbolAddress((void**)&pXhi, g_Xhi);
    cudaGetSymbolAddress((void**)&pXlo, g_Xlo);
    cudaGetSymbolAddress((void**)&pW1hi, g_W1hi);
    cudaGetSymbolAddress((void**)&pW1lo, g_W1lo);
    cudaGetSymbolAddress((void**)&pW2hi, g_W2hi);
    cudaGetSymbolAddress((void**)&pW2lo, g_W2lo);
    cudaGetSymbolAddress((void**)&pW3hi, g_W3hi);
    cudaGetSymbolAddress((void**)&pW3lo, g_W3lo);

    constexpr int SM128 = 3 * (2 * 16384 + 2 * 128 * 128);  // 196608
    constexpr int SM64  = 3 * (2 * 16384 + 2 * 64 * 128);   // 147456
    cudaFuncSetAttribute((gemm_mma<128, true>), cudaFuncAttributeMaxDynamicSharedMemorySize, SM128);
    cudaFuncSetAttribute((gemm_mma<64, false>), cudaFuncAttributeMaxDynamicSharedMemorySize, SM64);

    // fork: conversions (independent of edge prep) on a second stream
    cudaStream_t s2;
    cudaStreamCreateWithFlags(&s2, cudaStreamNonBlocking);
    cudaEvent_t evFork, evJoin;
    cudaEventCreateWithFlags(&evFork, cudaEventDisableTiming);
    cudaEventCreateWithFlags(&evJoin, cudaEventDisableTiming);
    cudaEventRecord(evFork, 0);
    cudaStreamWaitEvent(s2, evFork, 0);

    {
        size_t tX = (size_t)N_NODES * FEAT / 4;
        k_cvtX<<<(int)((tX + 255) / 256), 256, 0, s2>>>(x, pXhi, pXlo);
        int tW = W1_ELEMS + W2_ELEMS + W3_ELEMS;
        k_cvtWall<<<(tW + 255) / 256, 256, 0, s2>>>(W1, W2, W3);
    }
    cudaEventRecord(evJoin, s2);

    // main stream: graph prep chain
    k_init<<<(N_NODES + 255) / 256, 256>>>(ei);
    k_edges<<<(E_EDGES + 255) / 256, 256>>>(ei);
    k_scan<<<1, 1024>>>();
    k_fill<<<(E_EDGES + N_NODES + 255) / 256, 256>>>();

    cudaStreamWaitEvent(0, evJoin, 0);
    cudaStreamDestroy(s2);
    cudaEventDestroy(evFork);
    cudaEventDestroy(evJoin);

    const int NT = (N_NODES + 127) / 128;   // 391 row tiles

    // layer 1: mma GEMM (K=512) -> fp16 bufH ; agg+BN+ReLU -> bf16 hi/lo
    gemm_mma<128, true><<<dim3(NT, 2), 256, SM128>>>(pXhi, pXlo, pW1hi, pW1lo, pH, N_NODES, FEAT, HID);
    agg_h2b<<<(N_NODES + 7) / 8, 256>>>(pH, pXhi, pXlo, b1, gamma, beta, mean, var);

    // layer 2: mma GEMM (K=256) -> fp16 bufH ; agg+BN+ReLU -> bf16 hi/lo
    gemm_mma<128, true><<<dim3(NT, 2), 256, SM128>>>(pXhi, pXlo, pW2hi, pW2lo, pH, N_NODES, HID, HID);
    agg_h2b<<<(N_NODES + 7) / 8, 256>>>(pH, pXhi, pXlo, b2, gamma, beta, mean, var);

    // layer 3: mma GEMM (K=256, padded N=64) -> fp32 bufC ; agg + b3 -> out
    gemm_mma<64, false><<<dim3(NT, 1), 256, SM64>>>(pXhi, pXlo, pW3hi, pW3lo, pC, N_NODES, HID, CLSP);
    agg_out<<<(N_NODES + 7) / 8, 256>>>(pC, out, b3);
}